// round 2
// baseline (speedup 1.0000x reference)
#include <cuda_runtime.h>
#include <cstdint>

#define N_NODES 50000
#define N_EDGES 800000
#define D_MODEL 128
// heads = 8, head_dim = 16 (4 lanes per head, 4 floats per lane)

// ---------------- scratch (static device globals; no runtime alloc) ----------
__device__ __align__(256) float g_Q[(size_t)N_NODES * D_MODEL];
__device__ __align__(256) float g_K[(size_t)N_NODES * D_MODEL];
__device__ __align__(256) float g_V[(size_t)N_NODES * D_MODEL];
__device__ __align__(256) int   g_deg[N_NODES];
__device__ __align__(256) int   g_start[N_NODES + 1];
__device__ __align__(256) int   g_cursor[N_NODES];
__device__ __align__(256) int   g_csr_col[N_EDGES];
__device__ int g_is64;   // 1 if edge_index is int64, 0 if int32

// ---------------- edge dtype detection ---------------------------------------
// int64 little-endian with values in [0, 50000): every odd 32-bit word is 0.
// Random int32 values in [0, 50000): odd words are ~never all zero over 1024.
__global__ void detect_kernel(const int* __restrict__ raw) {
    const int lane = threadIdx.x & 31;
    int acc = 0;
    for (int i = lane; i < 1024; i += 32)
        acc |= raw[2 * i + 1];
#pragma unroll
    for (int o = 16; o > 0; o >>= 1)
        acc |= __shfl_xor_sync(0xffffffffu, acc, o);
    if (lane == 0) g_is64 = (acc == 0) ? 1 : 0;
}

__device__ __forceinline__ int load_edge(const void* p, int is64, size_t idx) {
    int v;
    if (is64) v = (int)((const long long*)p)[idx];
    else      v = ((const int*)p)[idx];
    // clamp so a bad index shows up as rel_err, not an illegal access
    v = v < 0 ? 0 : (v >= N_NODES ? N_NODES - 1 : v);
    return v;
}

// ---------------- CSR build ---------------------------------------------------
__global__ void zero_deg_kernel() {
    int i = blockIdx.x * blockDim.x + threadIdx.x;
    if (i < N_NODES) g_deg[i] = 0;
}

__global__ void degree_kernel(const void* __restrict__ edge_index) {
    int e = blockIdx.x * blockDim.x + threadIdx.x;
    if (e < N_EDGES) {
        const int is64 = g_is64;
        int row = load_edge(edge_index, is64, e);   // edge_index[0][e]
        atomicAdd(&g_deg[row], 1);
    }
}

// single block, 1024 threads: exclusive scan of 50000 degrees
__global__ void scan_kernel() {
    __shared__ int partial[1024];
    const int tid = threadIdx.x;
    const int CH  = (N_NODES + 1023) / 1024;    // 49
    const int base = tid * CH;

    int sum = 0;
    for (int i = 0; i < CH; i++) {
        int idx = base + i;
        if (idx < N_NODES) sum += g_deg[idx];
    }
    partial[tid] = sum;
    __syncthreads();

    for (int off = 1; off < 1024; off <<= 1) {
        int v = (tid >= off) ? partial[tid - off] : 0;
        __syncthreads();
        partial[tid] += v;
        __syncthreads();
    }

    int run = (tid > 0) ? partial[tid - 1] : 0;  // exclusive prefix
    for (int i = 0; i < CH; i++) {
        int idx = base + i;
        if (idx < N_NODES) {
            g_start[idx]  = run;
            g_cursor[idx] = run;
            run += g_deg[idx];
        }
    }
    if (tid == 1023) g_start[N_NODES] = partial[1023];
}

__global__ void scatter_kernel(const void* __restrict__ edge_index) {
    int e = blockIdx.x * blockDim.x + threadIdx.x;
    if (e < N_EDGES) {
        const int is64 = g_is64;
        int row = load_edge(edge_index, is64, e);
        int col = load_edge(edge_index, is64, (size_t)N_EDGES + e);
        int idx = atomicAdd(&g_cursor[row], 1);
        if (idx >= 0 && idx < N_EDGES) g_csr_col[idx] = col;
    }
}

// ---------------- fused QKV projection ---------------------------------------
// warp handles 4 consecutive nodes; lane owns output cols [4*lane, 4*lane+4)
__global__ __launch_bounds__(256) void qkv_kernel(
    const float* __restrict__ emb,
    const float* __restrict__ Wq,
    const float* __restrict__ Wk,
    const float* __restrict__ Wv)
{
    const int warp = (blockIdx.x * blockDim.x + threadIdx.x) >> 5;
    const int lane = threadIdx.x & 31;
    const int n0 = warp * 4;
    if (n0 >= N_NODES) return;

    float4 e4[4];
#pragma unroll
    for (int i = 0; i < 4; i++)
        e4[i] = *(const float4*)(emb + (size_t)(n0 + i) * D_MODEL + lane * 4);

    float4 aq[4], ak[4], av[4];
#pragma unroll
    for (int i = 0; i < 4; i++) {
        aq[i] = make_float4(0.f, 0.f, 0.f, 0.f);
        ak[i] = make_float4(0.f, 0.f, 0.f, 0.f);
        av[i] = make_float4(0.f, 0.f, 0.f, 0.f);
    }

    for (int k0 = 0; k0 < D_MODEL; k0 += 4) {
        const int src = k0 >> 2;   // lane that owns elements k0..k0+3 of a row
#pragma unroll
        for (int j = 0; j < 4; j++) {
            const int k = k0 + j;
            const float4 wq = *(const float4*)(Wq + (size_t)k * D_MODEL + lane * 4);
            const float4 wk = *(const float4*)(Wk + (size_t)k * D_MODEL + lane * 4);
            const float4 wv = *(const float4*)(Wv + (size_t)k * D_MODEL + lane * 4);
#pragma unroll
            for (int i = 0; i < 4; i++) {
                float comp = (j == 0) ? e4[i].x : (j == 1) ? e4[i].y
                           : (j == 2) ? e4[i].z : e4[i].w;
                float val = __shfl_sync(0xffffffffu, comp, src);
                aq[i].x += val * wq.x; aq[i].y += val * wq.y;
                aq[i].z += val * wq.z; aq[i].w += val * wq.w;
                ak[i].x += val * wk.x; ak[i].y += val * wk.y;
                ak[i].z += val * wk.z; ak[i].w += val * wk.w;
                av[i].x += val * wv.x; av[i].y += val * wv.y;
                av[i].z += val * wv.z; av[i].w += val * wv.w;
            }
        }
    }

#pragma unroll
    for (int i = 0; i < 4; i++) {
        const size_t off = (size_t)(n0 + i) * D_MODEL + lane * 4;
        *(float4*)(g_Q + off) = aq[i];
        *(float4*)(g_K + off) = ak[i];
        *(float4*)(g_V + off) = av[i];
    }
}

// ---------------- fused attention + aggregate + residual + LayerNorm ----------
// warp per destination node; lane owns cols [4*lane, 4*lane+4)
// head h (16-wide) lives in lanes [4h, 4h+3]
__global__ __launch_bounds__(256) void attn_kernel(
    const float* __restrict__ emb,
    const float* __restrict__ ln_scale,
    const float* __restrict__ ln_bias,
    float* __restrict__ out)
{
    const int n = (blockIdx.x * blockDim.x + threadIdx.x) >> 5;
    const int lane = threadIdx.x & 31;
    if (n >= N_NODES) return;

    const float4 q4 = *(const float4*)(g_Q + (size_t)n * D_MODEL + lane * 4);
    float4 acc = make_float4(0.f, 0.f, 0.f, 0.f);
    float norm = 0.f;

    const int s = g_start[n];
    const int t = g_start[n + 1];
    for (int e = s; e < t; e++) {
        const int col = g_csr_col[e];
        const float4 k4 = *(const float4*)(g_K + (size_t)col * D_MODEL + lane * 4);
        float d = q4.x * k4.x + q4.y * k4.y + q4.z * k4.z + q4.w * k4.w;
        d += __shfl_xor_sync(0xffffffffu, d, 1);
        d += __shfl_xor_sync(0xffffffffu, d, 2);
        d = fminf(fmaxf(d, -10.f), 10.f);
        const float w = __expf(d);
        const float4 v4 = *(const float4*)(g_V + (size_t)col * D_MODEL + lane * 4);
        acc.x += w * v4.x; acc.y += w * v4.y;
        acc.z += w * v4.z; acc.w += w * v4.w;
        norm += w;
    }

    const float scale = 1.f / (norm + 1e-8f);
    const float4 e4 = *(const float4*)(emb + (size_t)n * D_MODEL + lane * 4);
    float4 r;
    r.x = acc.x * scale + e4.x;
    r.y = acc.y * scale + e4.y;
    r.z = acc.z * scale + e4.z;
    r.w = acc.w * scale + e4.w;

    // LayerNorm across 128 (full warp)
    float ssum = r.x + r.y + r.z + r.w;
    float ssq  = r.x * r.x + r.y * r.y + r.z * r.z + r.w * r.w;
#pragma unroll
    for (int o = 16; o > 0; o >>= 1) {
        ssum += __shfl_xor_sync(0xffffffffu, ssum, o);
        ssq  += __shfl_xor_sync(0xffffffffu, ssq,  o);
    }
    const float mu  = ssum * (1.f / 128.f);
    const float var = ssq * (1.f / 128.f) - mu * mu;
    const float inv = rsqrtf(var + 1e-6f);

    const float4 sc = *(const float4*)(ln_scale + lane * 4);
    const float4 bi = *(const float4*)(ln_bias + lane * 4);
    float4 o4;
    o4.x = (r.x - mu) * inv * sc.x + bi.x;
    o4.y = (r.y - mu) * inv * sc.y + bi.y;
    o4.z = (r.z - mu) * inv * sc.z + bi.z;
    o4.w = (r.w - mu) * inv * sc.w + bi.w;
    *(float4*)(out + (size_t)n * D_MODEL + lane * 4) = o4;
}

// ---------------- launch ------------------------------------------------------
extern "C" void kernel_launch(void* const* d_in, const int* in_sizes, int n_in,
                              void* d_out, int out_size)
{
    const float* emb      = (const float*)d_in[0];
    const void*  edge_idx = d_in[1];
    const float* Wq       = (const float*)d_in[2];
    const float* Wk       = (const float*)d_in[3];
    const float* Wv       = (const float*)d_in[4];
    const float* ln_s     = (const float*)d_in[5];
    const float* ln_b     = (const float*)d_in[6];
    float*       out      = (float*)d_out;

    detect_kernel<<<1, 32>>>((const int*)edge_idx);
    zero_deg_kernel<<<(N_NODES + 255) / 256, 256>>>();
    degree_kernel<<<(N_EDGES + 255) / 256, 256>>>(edge_idx);
    scan_kernel<<<1, 1024>>>();
    scatter_kernel<<<(N_EDGES + 255) / 256, 256>>>(edge_idx);

    // 12500 warps (4 nodes each), 8 warps/block
    qkv_kernel<<<(12500 + 7) / 8, 256>>>(emb, Wq, Wk, Wv);

    // 50000 warps (1 node each), 8 warps/block
    attn_kernel<<<(N_NODES + 7) / 8, 256>>>(emb, ln_s, ln_b, out);
}

// round 3
// speedup vs baseline: 1.3230x; 1.3230x over previous
#include <cuda_runtime.h>
#include <cstdint>

#define N_NODES 50000
#define N_EDGES 800000
#define D_MODEL 128
// heads = 8, head_dim = 16 (4 lanes per head, 4 floats per lane)

#define SCAN_BLK 256
#define SCAN_NBLK ((N_NODES + SCAN_BLK - 1) / SCAN_BLK)   // 196

// ---------------- scratch (static device globals; no runtime alloc) ----------
__device__ __align__(256) float g_Q[(size_t)N_NODES * D_MODEL];
__device__ __align__(256) float g_K[(size_t)N_NODES * D_MODEL];
__device__ __align__(256) float g_V[(size_t)N_NODES * D_MODEL];
__device__ __align__(256) int   g_deg[N_NODES];
__device__ __align__(256) int   g_start[N_NODES + 1];
__device__ __align__(256) int   g_cursor[N_NODES];
__device__ __align__(256) int   g_csr_col[N_EDGES];
__device__ __align__(256) int   g_blk_sum[SCAN_NBLK];
__device__ __align__(256) int   g_blk_off[SCAN_NBLK];
__device__ int g_is64;   // 1 if edge_index is int64, 0 if int32

// ---------------- packed f32x2 helpers ----------------------------------------
__device__ __forceinline__ unsigned long long pack2(float lo, float hi) {
    unsigned long long r;
    asm("mov.b64 %0, {%1, %2};" : "=l"(r) : "f"(lo), "f"(hi));
    return r;
}
__device__ __forceinline__ void fma2(unsigned long long& acc,
                                     unsigned long long a,
                                     unsigned long long b) {
    asm("fma.rn.f32x2 %0, %1, %2, %0;" : "+l"(acc) : "l"(a), "l"(b));
}
__device__ __forceinline__ float2 unpack2(unsigned long long v) {
    float lo, hi;
    asm("mov.b64 {%0, %1}, %2;" : "=f"(lo), "=f"(hi) : "l"(v));
    return make_float2(lo, hi);
}

// ---------------- edge dtype detection ---------------------------------------
__global__ void detect_kernel(const int* __restrict__ raw) {
    const int lane = threadIdx.x & 31;
    int acc = 0;
    for (int i = lane; i < 1024; i += 32)
        acc |= raw[2 * i + 1];
#pragma unroll
    for (int o = 16; o > 0; o >>= 1)
        acc |= __shfl_xor_sync(0xffffffffu, acc, o);
    if (lane == 0) g_is64 = (acc == 0) ? 1 : 0;
}

__device__ __forceinline__ int load_edge(const void* p, int is64, size_t idx) {
    int v;
    if (is64) v = (int)((const long long*)p)[idx];
    else      v = ((const int*)p)[idx];
    v = v < 0 ? 0 : (v >= N_NODES ? N_NODES - 1 : v);
    return v;
}

// ---------------- CSR build ---------------------------------------------------
__global__ void zero_deg_kernel() {
    int i = blockIdx.x * blockDim.x + threadIdx.x;
    if (i < N_NODES) g_deg[i] = 0;
}

__global__ void degree_kernel(const void* __restrict__ edge_index) {
    int e = blockIdx.x * blockDim.x + threadIdx.x;
    if (e < N_EDGES) {
        const int is64 = g_is64;
        int row = load_edge(edge_index, is64, e);
        atomicAdd(&g_deg[row], 1);
    }
}

// pass 1: per-block sums of g_deg (coalesced)
__global__ void scan_reduce_kernel() {
    __shared__ int wsum[SCAN_BLK / 32];
    const int i = blockIdx.x * SCAN_BLK + threadIdx.x;
    int d = (i < N_NODES) ? g_deg[i] : 0;
    int s = d;
#pragma unroll
    for (int o = 16; o > 0; o >>= 1) s += __shfl_xor_sync(0xffffffffu, s, o);
    if ((threadIdx.x & 31) == 0) wsum[threadIdx.x >> 5] = s;
    __syncthreads();
    if (threadIdx.x == 0) {
        int t = 0;
#pragma unroll
        for (int w = 0; w < SCAN_BLK / 32; w++) t += wsum[w];
        g_blk_sum[blockIdx.x] = t;
    }
}

// pass 2: one block scans the 196 block sums (exclusive)
__global__ void scan_spine_kernel() {
    __shared__ int sh[256];
    const int tid = threadIdx.x;
    int v = (tid < SCAN_NBLK) ? g_blk_sum[tid] : 0;
    sh[tid] = v;
    __syncthreads();
    for (int off = 1; off < 256; off <<= 1) {
        int u = (tid >= off) ? sh[tid - off] : 0;
        __syncthreads();
        sh[tid] += u;
        __syncthreads();
    }
    if (tid < SCAN_NBLK) g_blk_off[tid] = sh[tid] - v;   // exclusive
    if (tid == 0) g_start[N_NODES] = N_EDGES;
}

// pass 3: block-local exclusive scan + spine offset -> g_start / g_cursor
__global__ void scan_final_kernel() {
    __shared__ int wsum[SCAN_BLK / 32];
    const int tid  = threadIdx.x;
    const int lane = tid & 31;
    const int wid  = tid >> 5;
    const int i = blockIdx.x * SCAN_BLK + tid;

    int d = (i < N_NODES) ? g_deg[i] : 0;
    // warp inclusive scan
    int inc = d;
#pragma unroll
    for (int o = 1; o < 32; o <<= 1) {
        int u = __shfl_up_sync(0xffffffffu, inc, o);
        if (lane >= o) inc += u;
    }
    if (lane == 31) wsum[wid] = inc;
    __syncthreads();
    if (wid == 0) {
        int w = (lane < SCAN_BLK / 32) ? wsum[lane] : 0;
#pragma unroll
        for (int o = 1; o < SCAN_BLK / 32; o <<= 1) {
            int u = __shfl_up_sync(0xffffffffu, w, o);
            if (lane >= o) w += u;
        }
        if (lane < SCAN_BLK / 32) wsum[lane] = w;
    }
    __syncthreads();
    int base = g_blk_off[blockIdx.x] + (wid > 0 ? wsum[wid - 1] : 0);
    int excl = base + inc - d;
    if (i < N_NODES) {
        g_start[i]  = excl;
        g_cursor[i] = excl;
    }
}

__global__ void scatter_kernel(const void* __restrict__ edge_index) {
    int e = blockIdx.x * blockDim.x + threadIdx.x;
    if (e < N_EDGES) {
        const int is64 = g_is64;
        int row = load_edge(edge_index, is64, e);
        int col = load_edge(edge_index, is64, (size_t)N_EDGES + e);
        int idx = atomicAdd(&g_cursor[row], 1);
        if (idx >= 0 && idx < N_EDGES) g_csr_col[idx] = col;
    }
}

// ---------------- fused QKV projection (f32x2 packed math) --------------------
// warp handles 4 consecutive nodes; lane owns output cols [4*lane, 4*lane+4)
__global__ __launch_bounds__(256) void qkv_kernel(
    const float* __restrict__ emb,
    const float* __restrict__ Wq,
    const float* __restrict__ Wk,
    const float* __restrict__ Wv)
{
    const int warp = (blockIdx.x * blockDim.x + threadIdx.x) >> 5;
    const int lane = threadIdx.x & 31;
    const int n0 = warp * 4;
    if (n0 >= N_NODES) return;

    float4 e4[4];
#pragma unroll
    for (int i = 0; i < 4; i++)
        e4[i] = *(const float4*)(emb + (size_t)(n0 + i) * D_MODEL + lane * 4);

    // accumulators: [node][q/k/v][lo-pair, hi-pair]
    unsigned long long aq[4][2], ak[4][2], av[4][2];
#pragma unroll
    for (int i = 0; i < 4; i++) {
        aq[i][0] = aq[i][1] = 0ULL;   // 0x0 == {0.f, 0.f}
        ak[i][0] = ak[i][1] = 0ULL;
        av[i][0] = av[i][1] = 0ULL;
    }

    for (int k0 = 0; k0 < D_MODEL; k0 += 4) {
        const int src = k0 >> 2;
#pragma unroll
        for (int j = 0; j < 4; j++) {
            const int k = k0 + j;
            const ulonglong2 wq = *(const ulonglong2*)(Wq + (size_t)k * D_MODEL + lane * 4);
            const ulonglong2 wk = *(const ulonglong2*)(Wk + (size_t)k * D_MODEL + lane * 4);
            const ulonglong2 wv = *(const ulonglong2*)(Wv + (size_t)k * D_MODEL + lane * 4);
#pragma unroll
            for (int i = 0; i < 4; i++) {
                float comp = (j == 0) ? e4[i].x : (j == 1) ? e4[i].y
                           : (j == 2) ? e4[i].z : e4[i].w;
                float val = __shfl_sync(0xffffffffu, comp, src);
                unsigned long long v2 = pack2(val, val);
                fma2(aq[i][0], wq.x, v2); fma2(aq[i][1], wq.y, v2);
                fma2(ak[i][0], wk.x, v2); fma2(ak[i][1], wk.y, v2);
                fma2(av[i][0], wv.x, v2); fma2(av[i][1], wv.y, v2);
            }
        }
    }

#pragma unroll
    for (int i = 0; i < 4; i++) {
        const size_t off = (size_t)(n0 + i) * D_MODEL + lane * 4;
        *(ulonglong2*)(g_Q + off) = make_ulonglong2(aq[i][0], aq[i][1]);
        *(ulonglong2*)(g_K + off) = make_ulonglong2(ak[i][0], ak[i][1]);
        *(ulonglong2*)(g_V + off) = make_ulonglong2(av[i][0], av[i][1]);
    }
}

// ---------------- fused attention + aggregate + residual + LayerNorm ----------
// warp per destination node; lane owns cols [4*lane, 4*lane+4)
// head h (16-wide) lives in lanes [4h, 4h+3]
__global__ __launch_bounds__(256) void attn_kernel(
    const float* __restrict__ emb,
    const float* __restrict__ ln_scale,
    const float* __restrict__ ln_bias,
    float* __restrict__ out)
{
    const int n = (blockIdx.x * blockDim.x + threadIdx.x) >> 5;
    const int lane = threadIdx.x & 31;
    if (n >= N_NODES) return;

    const float4 q4 = *(const float4*)(g_Q + (size_t)n * D_MODEL + lane * 4);
    float4 acc = make_float4(0.f, 0.f, 0.f, 0.f);
    float norm = 0.f;

    const int s = g_start[n];
    const int t = g_start[n + 1];

    int col = (s < t) ? g_csr_col[s] : 0;
    for (int e = s; e < t; e++) {
        // prefetch next column index (hides the index->row dependent chain)
        const int col_nx = (e + 1 < t) ? g_csr_col[e + 1] : 0;
        // issue both gathers before consuming either
        const float4 k4 = *(const float4*)(g_K + (size_t)col * D_MODEL + lane * 4);
        const float4 v4 = *(const float4*)(g_V + (size_t)col * D_MODEL + lane * 4);

        float d = q4.x * k4.x + q4.y * k4.y + q4.z * k4.z + q4.w * k4.w;
        d += __shfl_xor_sync(0xffffffffu, d, 1);
        d += __shfl_xor_sync(0xffffffffu, d, 2);
        d = fminf(fmaxf(d, -10.f), 10.f);
        const float w = __expf(d);

        acc.x += w * v4.x; acc.y += w * v4.y;
        acc.z += w * v4.z; acc.w += w * v4.w;
        norm += w;
        col = col_nx;
    }

    const float scale = 1.f / (norm + 1e-8f);
    const float4 e4 = *(const float4*)(emb + (size_t)n * D_MODEL + lane * 4);
    float4 r;
    r.x = acc.x * scale + e4.x;
    r.y = acc.y * scale + e4.y;
    r.z = acc.z * scale + e4.z;
    r.w = acc.w * scale + e4.w;

    float ssum = r.x + r.y + r.z + r.w;
    float ssq  = r.x * r.x + r.y * r.y + r.z * r.z + r.w * r.w;
#pragma unroll
    for (int o = 16; o > 0; o >>= 1) {
        ssum += __shfl_xor_sync(0xffffffffu, ssum, o);
        ssq  += __shfl_xor_sync(0xffffffffu, ssq,  o);
    }
    const float mu  = ssum * (1.f / 128.f);
    const float var = ssq * (1.f / 128.f) - mu * mu;
    const float inv = rsqrtf(var + 1e-6f);

    const float4 sc = *(const float4*)(ln_scale + lane * 4);
    const float4 bi = *(const float4*)(ln_bias + lane * 4);
    float4 o4;
    o4.x = (r.x - mu) * inv * sc.x + bi.x;
    o4.y = (r.y - mu) * inv * sc.y + bi.y;
    o4.z = (r.z - mu) * inv * sc.z + bi.z;
    o4.w = (r.w - mu) * inv * sc.w + bi.w;
    *(float4*)(out + (size_t)n * D_MODEL + lane * 4) = o4;
}

// ---------------- launch ------------------------------------------------------
extern "C" void kernel_launch(void* const* d_in, const int* in_sizes, int n_in,
                              void* d_out, int out_size)
{
    const float* emb      = (const float*)d_in[0];
    const void*  edge_idx = d_in[1];
    const float* Wq       = (const float*)d_in[2];
    const float* Wk       = (const float*)d_in[3];
    const float* Wv       = (const float*)d_in[4];
    const float* ln_s     = (const float*)d_in[5];
    const float* ln_b     = (const float*)d_in[6];
    float*       out      = (float*)d_out;

    detect_kernel<<<1, 32>>>((const int*)edge_idx);
    zero_deg_kernel<<<(N_NODES + 255) / 256, 256>>>();
    degree_kernel<<<(N_EDGES + 255) / 256, 256>>>(edge_idx);

    scan_reduce_kernel<<<SCAN_NBLK, SCAN_BLK>>>();
    scan_spine_kernel<<<1, 256>>>();
    scan_final_kernel<<<SCAN_NBLK, SCAN_BLK>>>();

    scatter_kernel<<<(N_EDGES + 255) / 256, 256>>>(edge_idx);

    qkv_kernel<<<(12500 + 7) / 8, 256>>>(emb, Wq, Wk, Wv);
    attn_kernel<<<(N_NODES + 7) / 8, 256>>>(emb, ln_s, ln_b, out);
}

// round 4
// speedup vs baseline: 1.3348x; 1.0089x over previous
#include <cuda_runtime.h>
#include <cstdint>

#define N_NODES 50000
#define N_EDGES 800000
#define D_MODEL 128
// heads = 8, head_dim = 16 (4 lanes per head, 4 floats per lane)

#define SCAN_BLK 256
#define SCAN_NBLK ((N_NODES + SCAN_BLK - 1) / SCAN_BLK)   // 196

// ---------------- scratch (static device globals; no runtime alloc) ----------
__device__ __align__(256) float g_Q[(size_t)N_NODES * D_MODEL];
__device__ __align__(256) float g_K[(size_t)N_NODES * D_MODEL];
__device__ __align__(256) float g_V[(size_t)N_NODES * D_MODEL];
__device__ __align__(256) int   g_deg[N_NODES];
__device__ __align__(256) int   g_start[N_NODES + 1];
__device__ __align__(256) int   g_cursor[N_NODES];
__device__ __align__(256) int   g_csr_col[N_EDGES];
__device__ __align__(256) int   g_blk_sum[SCAN_NBLK];
__device__ __align__(256) int   g_blk_off[SCAN_NBLK];
__device__ int g_is64;       // 1 if edge_index is int64, 0 if int32
__device__ int g_spine_ctr;  // zero-init; invariant: 0 at kernel entry (reset by last block)

// ---------------- packed f32x2 helpers ----------------------------------------
__device__ __forceinline__ unsigned long long pack2(float lo, float hi) {
    unsigned long long r;
    asm("mov.b64 %0, {%1, %2};" : "=l"(r) : "f"(lo), "f"(hi));
    return r;
}
__device__ __forceinline__ void fma2(unsigned long long& acc,
                                     unsigned long long a,
                                     unsigned long long b) {
    asm("fma.rn.f32x2 %0, %1, %2, %0;" : "+l"(acc) : "l"(a), "l"(b));
}

// ---------------- edge index handling -----------------------------------------
__device__ __forceinline__ int load_edge(const void* p, int is64, size_t idx) {
    int v;
    if (is64) v = (int)((const long long*)p)[idx];
    else      v = ((const int*)p)[idx];
    v = v < 0 ? 0 : (v >= N_NODES ? N_NODES - 1 : v);
    return v;
}

// ---------------- 1: zero degrees + detect edge dtype --------------------------
// int64 little-endian with values in [0, 50000): every odd 32-bit word is 0.
__global__ void init_kernel(const int* __restrict__ raw) {
    const int i = blockIdx.x * blockDim.x + threadIdx.x;
    if (i < N_NODES) g_deg[i] = 0;
    if (blockIdx.x == 0 && threadIdx.x < 32) {
        const int lane = threadIdx.x;
        int acc = 0;
        for (int k = lane; k < 1024; k += 32)
            acc |= raw[2 * k + 1];
#pragma unroll
        for (int o = 16; o > 0; o >>= 1)
            acc |= __shfl_xor_sync(0xffffffffu, acc, o);
        if (lane == 0) g_is64 = (acc == 0) ? 1 : 0;
    }
}

// ---------------- 2: degree count ---------------------------------------------
__global__ void degree_kernel(const void* __restrict__ edge_index) {
    int e = blockIdx.x * blockDim.x + threadIdx.x;
    if (e < N_EDGES) {
        const int is64 = g_is64;
        int row = load_edge(edge_index, is64, e);
        atomicAdd(&g_deg[row], 1);
    }
}

// ---------------- 3: block sums + spine scan (last block) ----------------------
__global__ void scan_reduce_spine_kernel() {
    __shared__ int wsum[SCAN_BLK / 32];
    __shared__ int sh[256];
    __shared__ int is_last;
    const int tid = threadIdx.x;
    const int i = blockIdx.x * SCAN_BLK + tid;

    int d = (i < N_NODES) ? g_deg[i] : 0;
    int s = d;
#pragma unroll
    for (int o = 16; o > 0; o >>= 1) s += __shfl_xor_sync(0xffffffffu, s, o);
    if ((tid & 31) == 0) wsum[tid >> 5] = s;
    __syncthreads();
    if (tid == 0) {
        int t = 0;
#pragma unroll
        for (int w = 0; w < SCAN_BLK / 32; w++) t += wsum[w];
        g_blk_sum[blockIdx.x] = t;
        __threadfence();
        int tk = atomicAdd(&g_spine_ctr, 1);
        is_last = (tk == SCAN_NBLK - 1) ? 1 : 0;
    }
    __syncthreads();
    if (!is_last) return;

    __threadfence();   // acquire: all blocks' g_blk_sum writes now visible
    int v = (tid < SCAN_NBLK) ? g_blk_sum[tid] : 0;
    sh[tid] = v;
    __syncthreads();
    for (int off = 1; off < 256; off <<= 1) {
        int u = (tid >= off) ? sh[tid - off] : 0;
        __syncthreads();
        sh[tid] += u;
        __syncthreads();
    }
    if (tid < SCAN_NBLK) g_blk_off[tid] = sh[tid] - v;   // exclusive
    if (tid == 0) {
        g_start[N_NODES] = N_EDGES;
        g_spine_ctr = 0;   // reset for next graph replay
    }
}

// ---------------- 4: block-local exclusive scan + spine offset -----------------
__global__ void scan_final_kernel() {
    __shared__ int wsum[SCAN_BLK / 32];
    const int tid  = threadIdx.x;
    const int lane = tid & 31;
    const int wid  = tid >> 5;
    const int i = blockIdx.x * SCAN_BLK + tid;

    int d = (i < N_NODES) ? g_deg[i] : 0;
    int inc = d;
#pragma unroll
    for (int o = 1; o < 32; o <<= 1) {
        int u = __shfl_up_sync(0xffffffffu, inc, o);
        if (lane >= o) inc += u;
    }
    if (lane == 31) wsum[wid] = inc;
    __syncthreads();
    if (wid == 0) {
        int w = (lane < SCAN_BLK / 32) ? wsum[lane] : 0;
#pragma unroll
        for (int o = 1; o < SCAN_BLK / 32; o <<= 1) {
            int u = __shfl_up_sync(0xffffffffu, w, o);
            if (lane >= o) w += u;
        }
        if (lane < SCAN_BLK / 32) wsum[lane] = w;
    }
    __syncthreads();
    int base = g_blk_off[blockIdx.x] + (wid > 0 ? wsum[wid - 1] : 0);
    int excl = base + inc - d;
    if (i < N_NODES) {
        g_start[i]  = excl;
        g_cursor[i] = excl;
    }
}

// ---------------- 5: scatter cols into CSR -------------------------------------
__global__ void scatter_kernel(const void* __restrict__ edge_index) {
    int e = blockIdx.x * blockDim.x + threadIdx.x;
    if (e < N_EDGES) {
        const int is64 = g_is64;
        int row = load_edge(edge_index, is64, e);
        int col = load_edge(edge_index, is64, (size_t)N_EDGES + e);
        int idx = atomicAdd(&g_cursor[row], 1);
        if (idx >= 0 && idx < N_EDGES) g_csr_col[idx] = col;
    }
}

// ---------------- 6: fused QKV projection (f32x2 packed math) ------------------
// warp handles 4 consecutive nodes; lane owns output cols [4*lane, 4*lane+4)
__global__ __launch_bounds__(256) void qkv_kernel(
    const float* __restrict__ emb,
    const float* __restrict__ Wq,
    const float* __restrict__ Wk,
    const float* __restrict__ Wv)
{
    const int warp = (blockIdx.x * blockDim.x + threadIdx.x) >> 5;
    const int lane = threadIdx.x & 31;
    const int n0 = warp * 4;
    if (n0 >= N_NODES) return;

    float4 e4[4];
#pragma unroll
    for (int i = 0; i < 4; i++)
        e4[i] = *(const float4*)(emb + (size_t)(n0 + i) * D_MODEL + lane * 4);

    unsigned long long aq[4][2], ak[4][2], av[4][2];
#pragma unroll
    for (int i = 0; i < 4; i++) {
        aq[i][0] = aq[i][1] = 0ULL;
        ak[i][0] = ak[i][1] = 0ULL;
        av[i][0] = av[i][1] = 0ULL;
    }

    for (int k0 = 0; k0 < D_MODEL; k0 += 4) {
        const int src = k0 >> 2;
#pragma unroll
        for (int j = 0; j < 4; j++) {
            const int k = k0 + j;
            const ulonglong2 wq = *(const ulonglong2*)(Wq + (size_t)k * D_MODEL + lane * 4);
            const ulonglong2 wk = *(const ulonglong2*)(Wk + (size_t)k * D_MODEL + lane * 4);
            const ulonglong2 wv = *(const ulonglong2*)(Wv + (size_t)k * D_MODEL + lane * 4);
#pragma unroll
            for (int i = 0; i < 4; i++) {
                float comp = (j == 0) ? e4[i].x : (j == 1) ? e4[i].y
                           : (j == 2) ? e4[i].z : e4[i].w;
                float val = __shfl_sync(0xffffffffu, comp, src);
                unsigned long long v2 = pack2(val, val);
                fma2(aq[i][0], wq.x, v2); fma2(aq[i][1], wq.y, v2);
                fma2(ak[i][0], wk.x, v2); fma2(ak[i][1], wk.y, v2);
                fma2(av[i][0], wv.x, v2); fma2(av[i][1], wv.y, v2);
            }
        }
    }

#pragma unroll
    for (int i = 0; i < 4; i++) {
        const size_t off = (size_t)(n0 + i) * D_MODEL + lane * 4;
        *(ulonglong2*)(g_Q + off) = make_ulonglong2(aq[i][0], aq[i][1]);
        *(ulonglong2*)(g_K + off) = make_ulonglong2(ak[i][0], ak[i][1]);
        *(ulonglong2*)(g_V + off) = make_ulonglong2(av[i][0], av[i][1]);
    }
}

// ---------------- 7: attention + aggregate + residual + LayerNorm --------------
__device__ __forceinline__ void edge_step(const float4 q4, const float4 k4,
                                          const float4 v4, float4& acc, float& norm) {
    float d = q4.x * k4.x + q4.y * k4.y + q4.z * k4.z + q4.w * k4.w;
    d += __shfl_xor_sync(0xffffffffu, d, 1);
    d += __shfl_xor_sync(0xffffffffu, d, 2);
    d = fminf(fmaxf(d, -10.f), 10.f);
    const float w = __expf(d);
    acc.x += w * v4.x; acc.y += w * v4.y;
    acc.z += w * v4.z; acc.w += w * v4.w;
    norm += w;
}

// warp per destination node; lane owns cols [4*lane, 4*lane+4)
// head h (16-wide) lives in lanes [4h, 4h+3]
__global__ __launch_bounds__(256) void attn_kernel(
    const float* __restrict__ emb,
    const float* __restrict__ ln_scale,
    const float* __restrict__ ln_bias,
    float* __restrict__ out)
{
    const int n = (blockIdx.x * blockDim.x + threadIdx.x) >> 5;
    const int lane = threadIdx.x & 31;
    if (n >= N_NODES) return;

    const float4 q4 = *(const float4*)(g_Q + (size_t)n * D_MODEL + lane * 4);
    float4 acc = make_float4(0.f, 0.f, 0.f, 0.f);
    float norm = 0.f;

    const int s = g_start[n];
    const int t = g_start[n + 1];
    const size_t loff = (size_t)lane * 4;

    // 2-wide, 2-deep software pipeline: 4 independent float4 gathers in flight
    int cA = (s     < t) ? g_csr_col[s]     : 0;
    int cB = (s + 1 < t) ? g_csr_col[s + 1] : 0;
    float4 k0 = *(const float4*)(g_K + (size_t)cA * D_MODEL + loff);
    float4 v0 = *(const float4*)(g_V + (size_t)cA * D_MODEL + loff);
    float4 k1 = *(const float4*)(g_K + (size_t)cB * D_MODEL + loff);
    float4 v1 = *(const float4*)(g_V + (size_t)cB * D_MODEL + loff);

    int e = s;
    for (; e + 1 < t; e += 2) {
        const int c2 = (e + 2 < t) ? g_csr_col[e + 2] : 0;
        const int c3 = (e + 3 < t) ? g_csr_col[e + 3] : 0;
        const float4 nk0 = *(const float4*)(g_K + (size_t)c2 * D_MODEL + loff);
        const float4 nv0 = *(const float4*)(g_V + (size_t)c2 * D_MODEL + loff);
        const float4 nk1 = *(const float4*)(g_K + (size_t)c3 * D_MODEL + loff);
        const float4 nv1 = *(const float4*)(g_V + (size_t)c3 * D_MODEL + loff);

        edge_step(q4, k0, v0, acc, norm);
        edge_step(q4, k1, v1, acc, norm);

        k0 = nk0; v0 = nv0; k1 = nk1; v1 = nv1;
    }
    if (e < t) edge_step(q4, k0, v0, acc, norm);   // odd tail

    const float scale = 1.f / (norm + 1e-8f);
    const float4 e4 = *(const float4*)(emb + (size_t)n * D_MODEL + loff);
    float4 r;
    r.x = acc.x * scale + e4.x;
    r.y = acc.y * scale + e4.y;
    r.z = acc.z * scale + e4.z;
    r.w = acc.w * scale + e4.w;

    float ssum = r.x + r.y + r.z + r.w;
    float ssq  = r.x * r.x + r.y * r.y + r.z * r.z + r.w * r.w;
#pragma unroll
    for (int o = 16; o > 0; o >>= 1) {
        ssum += __shfl_xor_sync(0xffffffffu, ssum, o);
        ssq  += __shfl_xor_sync(0xffffffffu, ssq,  o);
    }
    const float mu  = ssum * (1.f / 128.f);
    const float var = ssq * (1.f / 128.f) - mu * mu;
    const float inv = rsqrtf(var + 1e-6f);

    const float4 sc = *(const float4*)(ln_scale + loff);
    const float4 bi = *(const float4*)(ln_bias + loff);
    float4 o4;
    o4.x = (r.x - mu) * inv * sc.x + bi.x;
    o4.y = (r.y - mu) * inv * sc.y + bi.y;
    o4.z = (r.z - mu) * inv * sc.z + bi.z;
    o4.w = (r.w - mu) * inv * sc.w + bi.w;
    *(float4*)(out + (size_t)n * D_MODEL + loff) = o4;
}

// ---------------- launch ------------------------------------------------------
extern "C" void kernel_launch(void* const* d_in, const int* in_sizes, int n_in,
                              void* d_out, int out_size)
{
    const float* emb      = (const float*)d_in[0];
    const void*  edge_idx = d_in[1];
    const float* Wq       = (const float*)d_in[2];
    const float* Wk       = (const float*)d_in[3];
    const float* Wv       = (const float*)d_in[4];
    const float* ln_s     = (const float*)d_in[5];
    const float* ln_b     = (const float*)d_in[6];
    float*       out      = (float*)d_out;

    init_kernel<<<SCAN_NBLK, SCAN_BLK>>>((const int*)edge_idx);        // 1
    degree_kernel<<<(N_EDGES + 255) / 256, 256>>>(edge_idx);           // 2
    scan_reduce_spine_kernel<<<SCAN_NBLK, SCAN_BLK>>>();               // 3
    scan_final_kernel<<<SCAN_NBLK, SCAN_BLK>>>();                      // 4
    scatter_kernel<<<(N_EDGES + 255) / 256, 256>>>(edge_idx);          // 5
    qkv_kernel<<<(12500 + 7) / 8, 256>>>(emb, Wq, Wk, Wv);             // 6 <- ncu -s 5 -c 1
    attn_kernel<<<(N_NODES + 7) / 8, 256>>>(emb, ln_s, ln_b, out);     // 7
}